// round 2
// baseline (speedup 1.0000x reference)
#include <cuda_runtime.h>

#define BATCH 16
#define CHN   8
#define HH    512
#define WW    512
#define TW    128   // tile width (pixels)
#define TH    8     // tile height (rows)
#define BX    16    // threads x (each does 8 px)
#define BYT   8     // threads y (1 row each)
#define TILES_X (WW / TW)   // 4
#define TILES_Y (HH / TH)   // 64
#define NBLK (TILES_X * TILES_Y * BATCH)  // 4096
#define PITCH 132   // smem row pitch in floats (cols 0..129 used)

// Scratch (device globals: allocation-free rule)
__device__ float g_y[BATCH * CHN * HH * WW];     // conv output (134 MB)
__device__ float g_part[NBLK * 16];              // per-block [sum[8], sumsq[8]]
__device__ float g_scale[CHN];
__device__ float g_shift[CHN];

// ---------- f32x2 helpers ----------
__device__ __forceinline__ unsigned long long pk2(float lo, float hi) {
    unsigned long long r;
    asm("mov.b64 %0, {%1, %2};" : "=l"(r) : "f"(lo), "f"(hi));
    return r;
}
__device__ __forceinline__ void fma2(unsigned long long& d, unsigned long long a,
                                     unsigned long long b) {
    asm("fma.rn.f32x2 %0, %1, %2, %0;" : "+l"(d) : "l"(a), "l"(b));
}
__device__ __forceinline__ void add2(unsigned long long& d, unsigned long long a) {
    asm("add.rn.f32x2 %0, %0, %1;" : "+l"(d) : "l"(a));
}
__device__ __forceinline__ float2 up2(unsigned long long v) {
    float2 f;
    asm("mov.b64 {%0, %1}, %2;" : "=f"(f.x), "=f"(f.y) : "l"(v));
    return f;
}

// ---------- Kernel 1: conv3x3 + bias -> g_y, per-block channel sum/sumsq ----------
__global__ __launch_bounds__(BX * BYT, 4) void conv_kernel(
    const float* __restrict__ x, const float* __restrict__ lin_w,
    const float* __restrict__ lin_b) {
    __shared__ float s_in[CHN * (TH + 2) * PITCH];          // 42240 B
    __shared__ float2 s_w[CHN * 9 * 8];                     // duplicated (w,w): 4608 B
    __shared__ float2 s_bias[8];

    const int tx = threadIdx.x, ty = threadIdx.y;
    const int tid = ty * BX + tx;
    const int bw = blockIdx.x, bh = blockIdx.y, b = blockIdx.z;
    const int col0 = bw * TW, row0 = bh * TH;

    // Weights: s_w[(cin*9 + kh*3+kw)*8 + cout] = (w, w)
    for (int i = tid; i < CHN * 9 * 8; i += BX * BYT) {
        int cout = i & 7;
        int t = (i >> 3) % 9;
        int cin = i / 72;
        float w = lin_w[(cin * 8 + cout) * 9 + t];
        s_w[i] = make_float2(w, w);
    }
    if (tid < 8) {
        float bs = 0.f;
        #pragma unroll
        for (int cin = 0; cin < 8; cin++) bs += lin_b[cin * 8 + tid];
        s_bias[tid] = make_float2(bs, bs);
    }

    // Stage input tile: sr in [0,TH+2) -> row row0+sr-1 ; sc in [0,130) -> col col0+sc-1
    for (int i = tid; i < CHN * (TH + 2) * 130; i += BX * BYT) {
        int sc = i % 130;
        int t = i / 130;
        int sr = t % (TH + 2);
        int c = t / (TH + 2);
        int gr = row0 + sr - 1;
        int gc = col0 + sc - 1;
        float v = 0.f;
        if ((unsigned)gr < HH && (unsigned)gc < WW)
            v = x[((b * CHN + c) * HH + gr) * WW + gc];
        s_in[(c * (TH + 2) + sr) * PITCH + sc] = v;
    }
    __syncthreads();

    // Accumulators: 8 couts x 4 pixel-pairs (8 px), init = bias
    unsigned long long acc[8][4];
    #pragma unroll
    for (int co = 0; co < 8; co++) {
        unsigned long long bz = ((const unsigned long long*)s_bias)[co];
        acc[co][0] = bz; acc[co][1] = bz; acc[co][2] = bz; acc[co][3] = bz;
    }

    const unsigned long long* __restrict__ swp = (const unsigned long long*)s_w;
    const int scb = tx * 8;

    #pragma unroll 1
    for (int cin = 0; cin < 8; cin++) {
        const unsigned long long* wrow = swp + cin * 72;
        #pragma unroll
        for (int kh = 0; kh < 3; kh++) {
            const float* ip = &s_in[(cin * (TH + 2) + (ty + kh)) * PITCH + scb];
            float4 va = *(const float4*)ip;          // w0..w3
            float4 vb = *(const float4*)(ip + 4);    // w4..w7
            float2 vc = *(const float2*)(ip + 8);    // w8,w9
            unsigned long long E0 = pk2(va.x, va.y);
            unsigned long long E1 = pk2(va.z, va.w);
            unsigned long long E2 = pk2(vb.x, vb.y);
            unsigned long long E3 = pk2(vb.z, vb.w);
            unsigned long long E4 = pk2(vc.x, vc.y);
            unsigned long long O0 = pk2(va.y, va.z);
            unsigned long long O1 = pk2(va.w, vb.x);
            unsigned long long O2 = pk2(vb.y, vb.z);
            unsigned long long O3 = pk2(vb.w, vc.x);
            #pragma unroll
            for (int co = 0; co < 8; co++) {
                unsigned long long wA = wrow[(kh * 3 + 0) * 8 + co];
                fma2(acc[co][0], E0, wA);
                fma2(acc[co][1], E1, wA);
                fma2(acc[co][2], E2, wA);
                fma2(acc[co][3], E3, wA);
                unsigned long long wB = wrow[(kh * 3 + 1) * 8 + co];
                fma2(acc[co][0], O0, wB);
                fma2(acc[co][1], O1, wB);
                fma2(acc[co][2], O2, wB);
                fma2(acc[co][3], O3, wB);
                unsigned long long wC = wrow[(kh * 3 + 2) * 8 + co];
                fma2(acc[co][0], E1, wC);
                fma2(acc[co][1], E2, wC);
                fma2(acc[co][2], E3, wC);
                fma2(acc[co][3], E4, wC);
            }
        }
    }

    // Store y + thread-local channel sums
    const int orow = row0 + ty;
    float vals[16];
    #pragma unroll
    for (int co = 0; co < 8; co++) {
        int off = ((b * 8 + co) * HH + orow) * WW + col0 + scb;
        *(ulonglong2*)(g_y + off) = make_ulonglong2(acc[co][0], acc[co][1]);
        *(ulonglong2*)(g_y + off + 4) = make_ulonglong2(acc[co][2], acc[co][3]);
        unsigned long long ss = 0ull, sq = 0ull;
        #pragma unroll
        for (int p = 0; p < 4; p++) {
            add2(ss, acc[co][p]);
            fma2(sq, acc[co][p], acc[co][p]);
        }
        float2 fs = up2(ss), fq = up2(sq);
        vals[co] = fs.x + fs.y;
        vals[8 + co] = fq.x + fq.y;
    }

    // Warp reduce (4 warps of 32)
    #pragma unroll
    for (int v = 0; v < 16; v++) {
        float t = vals[v];
        #pragma unroll
        for (int o = 16; o > 0; o >>= 1) t += __shfl_xor_sync(0xFFFFFFFFu, t, o);
        vals[v] = t;
    }
    __syncthreads();  // done with s_in; reuse as reduction scratch
    float* sred = s_in;  // 4 warps * 16
    int wid = tid >> 5, lane = tid & 31;
    if (lane == 0) {
        #pragma unroll
        for (int v = 0; v < 16; v++) sred[wid * 16 + v] = vals[v];
    }
    __syncthreads();
    if (tid < 16) {
        float t = sred[tid] + sred[16 + tid] + sred[32 + tid] + sred[48 + tid];
        int blin = (b * gridDim.y + bh) * gridDim.x + bw;
        g_part[blin * 16 + tid] = t;
    }
}

// ---------- Kernel 2: finalize statistics ----------
__global__ void stats_kernel(const float* __restrict__ gamma,
                             const float* __restrict__ beta) {
    __shared__ float red[256];
    int tid = threadIdx.x;
    int v = tid & 15, g = tid >> 4;
    float s = 0.f;
    for (int i = g; i < NBLK; i += 16) s += g_part[i * 16 + v];
    red[tid] = s;
    __syncthreads();
    float tot = 0.f;
    if (tid < 16) {
        #pragma unroll
        for (int gg = 0; gg < 16; gg++) tot += red[gg * 16 + tid];
    }
    __syncthreads();
    if (tid < 16) red[tid] = tot;
    __syncthreads();
    if (tid < 8) {
        const float n = (float)(BATCH * HH * WW);
        float mean = red[tid] / n;
        float var = red[tid + 8] / n - mean * mean;
        float sc = gamma[tid] * rsqrtf(var + 1e-5f);
        g_scale[tid] = sc;
        g_shift[tid] = beta[tid] - mean * sc;
    }
}

// ---------- Kernel 3: normalize + ReLU ----------
__global__ __launch_bounds__(256) void norm_kernel(float* __restrict__ out) {
    __shared__ float ssc[8], ssh[8];
    if (threadIdx.x < 8) {
        ssc[threadIdx.x] = g_scale[threadIdx.x];
        ssh[threadIdx.x] = g_shift[threadIdx.x];
    }
    __syncthreads();
    int i = blockIdx.x * 256 + threadIdx.x;           // float4 index
    int c = (i >> 16) & 7;                            // 65536 float4 per channel
    float4 v = ((const float4*)g_y)[i];
    float s = ssc[c], h = ssh[c];
    v.x = fmaxf(fmaf(v.x, s, h), 0.f);
    v.y = fmaxf(fmaf(v.y, s, h), 0.f);
    v.z = fmaxf(fmaf(v.z, s, h), 0.f);
    v.w = fmaxf(fmaf(v.w, s, h), 0.f);
    ((float4*)out)[i] = v;
}

extern "C" void kernel_launch(void* const* d_in, const int* in_sizes, int n_in,
                              void* d_out, int out_size) {
    const float* x     = (const float*)d_in[0];
    const float* lin_w = (const float*)d_in[1];
    const float* lin_b = (const float*)d_in[2];
    const float* gamma = (const float*)d_in[3];
    const float* beta  = (const float*)d_in[4];
    float* out = (float*)d_out;

    dim3 grid(TILES_X, TILES_Y, BATCH);
    dim3 block(BX, BYT);
    conv_kernel<<<grid, block>>>(x, lin_w, lin_b);
    stats_kernel<<<1, 256>>>(gamma, beta);
    int n4 = BATCH * CHN * HH * WW / 4;   // 8388608
    norm_kernel<<<n4 / 256, 256>>>(out);
}